// round 12
// baseline (speedup 1.0000x reference)
#include <cuda_runtime.h>
#include <math_constants.h>

// Problem constants
#define NUM_VARS 64
#define KK       32
#define NUM_CATS 256
#define NUM_INPUT (NUM_VARS * KK)   // 2048
#define LL       4
#define EE       16384
#define NN       8192
#define CC       4
#define BB       1024
#define Q4       (BB / 4)           // 256 uint2-groups per row
#define ROWB     2048               // bytes per node row (1024 x u16)
#define TOTAL_NODES (NUM_INPUT + LL * NN)  // 34816
#define NCHUNK   64
#define MAX_NPB  14                 // max nodes per block per layer

#define GRID_BLOCKS 592             // 4 blocks/SM on 148 SMs — co-resident
#define THREADS     256
#define NTHREADS    (GRID_BLOCKS * THREADS)

#define LOG2E 1.4426950408889634f
#define LN2   0.6931471805599453f
#define QSCALE   128.0f             // u16 = -v_log2 * 128, clamp 32767
#define INVQ     (1.0f / 128.0f)
#define MAGIC    8388608.0f         // 2^23
#define MAGIC_HI 0x4B000000u

// Node pool quantized to u16 (71.3 MB — fully L2-resident)
__device__ unsigned short g_node_q[(size_t)TOTAL_NODES * BB];
__device__ float g_partial[NCHUNK * BB];
__device__ uint2 g_pairs[LL * NN * CC];   // BYTE offsets of the two product rows

// Grid barrier
__device__ unsigned g_bar_count;
__device__ volatile unsigned g_bar_gen;

__device__ __forceinline__ void grid_sync() {
    __syncthreads();
    if (threadIdx.x == 0) {
        __threadfence();
        unsigned gen = g_bar_gen;
        if (atomicAdd(&g_bar_count, 1u) == GRID_BLOCKS - 1u) {
            g_bar_count = 0;
            __threadfence();
            g_bar_gen = gen + 1u;
        } else {
            while (g_bar_gen == gen) { }
        }
    }
    __syncthreads();
    __threadfence();
}

__device__ __forceinline__ float ex2(float x) {
    float r; asm("ex2.approx.ftz.f32 %0, %1;" : "=f"(r) : "f"(x)); return r;
}
__device__ __forceinline__ float lg2(float x) {
    float r; asm("lg2.approx.ftz.f32 %0, %1;" : "=f"(r) : "f"(x)); return r;
}
__device__ __forceinline__ float lse4_2(float a, float b, float c, float d) {
    float m = fmaxf(fmaxf(a, b), fmaxf(c, d));
    float s = ex2(a - m) + ex2(b - m) + ex2(c - m) + ex2(d - m);
    return m + lg2(s);
}
__device__ __forceinline__ float dec_lo(unsigned s, float wq) {
    const float f = __uint_as_float(__byte_perm(s, MAGIC_HI, 0x7610));
    return fmaf(f, -INVQ, wq);
}
__device__ __forceinline__ float dec_hi(unsigned s, float wq) {
    const float f = __uint_as_float(__byte_perm(s, MAGIC_HI, 0x7632));
    return fmaf(f, -INVQ, wq);
}
__device__ __forceinline__ unsigned enc1(float v_log2) {
    unsigned q = __float2uint_rn(-v_log2 * QSCALE);
    return umin(q, 32767u);
}
__device__ __forceinline__ uint2 lds64(unsigned addr) {
    uint2 v;
    asm volatile("ld.shared.v2.u32 {%0,%1}, [%2];" : "=r"(v.x), "=r"(v.y) : "r"(addr));
    return v;
}

// cp.async prefetch of one node's 8 rows (16KB) into a smem buffer.
// 256 threads x 4 x 16B chunks. slot order matches g_pairs flattening.
__device__ __forceinline__ void prefetch_node(const unsigned* s_pairs, int i,
                                              unsigned sbuf, const char* gbase,
                                              int tid) {
    const int rsel  = tid >> 7;           // 0 or 1
    const int chunk = (tid & 127) << 4;   // byte offset within a row
#pragma unroll
    for (int j = 0; j < 4; j++) {
        const int slot = j * 2 + rsel;
        const char* src = gbase + (size_t)s_pairs[i * 8 + slot] + chunk;
        const unsigned dst = sbuf + slot * ROWB + chunk;
        const unsigned long long sg = (unsigned long long)__cvta_generic_to_global(src);
        asm volatile("cp.async.cg.shared.global [%0], [%1], 16;" :: "r"(dst), "l"(sg));
    }
}

__device__ __forceinline__ void compute_store(unsigned sbuf, const float4* s_w, int i,
                                              uint2* __restrict__ nqo,
                                              unsigned row, unsigned c4) {
    const unsigned off = c4 * 8;
    const uint2 a0 = lds64(sbuf + 0 * ROWB + off);
    const uint2 q0 = lds64(sbuf + 1 * ROWB + off);
    const uint2 a1 = lds64(sbuf + 2 * ROWB + off);
    const uint2 q1 = lds64(sbuf + 3 * ROWB + off);
    const uint2 a2 = lds64(sbuf + 4 * ROWB + off);
    const uint2 q2 = lds64(sbuf + 5 * ROWB + off);
    const uint2 a3 = lds64(sbuf + 6 * ROWB + off);
    const uint2 q3 = lds64(sbuf + 7 * ROWB + off);

    const float4 w = s_w[i];
    const float wq0 = fmaf(w.x, LOG2E, MAGIC * INVQ);
    const float wq1 = fmaf(w.y, LOG2E, MAGIC * INVQ);
    const float wq2 = fmaf(w.z, LOG2E, MAGIC * INVQ);
    const float wq3 = fmaf(w.w, LOG2E, MAGIC * INVQ);

    const unsigned s0x = __vadd2(a0.x, q0.x), s0y = __vadd2(a0.y, q0.y);
    const unsigned s1x = __vadd2(a1.x, q1.x), s1y = __vadd2(a1.y, q1.y);
    const unsigned s2x = __vadd2(a2.x, q2.x), s2y = __vadd2(a2.y, q2.y);
    const unsigned s3x = __vadd2(a3.x, q3.x), s3y = __vadd2(a3.y, q3.y);

    const float o0 = lse4_2(dec_lo(s0x, wq0), dec_lo(s1x, wq1),
                            dec_lo(s2x, wq2), dec_lo(s3x, wq3));
    const float o1 = lse4_2(dec_hi(s0x, wq0), dec_hi(s1x, wq1),
                            dec_hi(s2x, wq2), dec_hi(s3x, wq3));
    const float o2 = lse4_2(dec_lo(s0y, wq0), dec_lo(s1y, wq1),
                            dec_lo(s2y, wq2), dec_lo(s3y, wq3));
    const float o3 = lse4_2(dec_hi(s0y, wq0), dec_hi(s1y, wq1),
                            dec_hi(s2y, wq2), dec_hi(s3y, wq3));

    uint2 qo;
    qo.x = __byte_perm(enc1(o0), enc1(o1), 0x5410);
    qo.y = __byte_perm(enc1(o2), enc1(o3), 0x5410);
    nqo[row * Q4 + c4] = qo;
}

__global__ void __launch_bounds__(THREADS, 4)
circuit_kernel(const int* __restrict__ inputs,
               const float* __restrict__ input_logp,
               const int2* __restrict__ prod_ids,     // (L, E)
               const int* __restrict__ sum_ch_ids,    // (L, N, C)
               const float4* __restrict__ sum_logw,   // (L, N) as float4
               const float* __restrict__ root_logw,   // (N,)
               float* __restrict__ out) {
    const int gtid = blockIdx.x * THREADS + threadIdx.x;
    const int tid = threadIdx.x;

    __shared__ __align__(16) char s_buf[2][8 * ROWB];   // 32 KB double buffer
    __shared__ unsigned s_pairs[MAX_NPB * 8];
    __shared__ float4   s_w[MAX_NPB];

    // ---------- Phase 0: input quantize + resolve (byte offsets) ---------------
    for (int idx = gtid; idx < NUM_INPUT * BB; idx += NTHREADS) {
        const int v = idx >> 15;
        const int k = (idx >> 10) & (KK - 1);
        const int b = idx & (BB - 1);
        const int cat = __ldg(inputs + b * NUM_VARS + v);
        const float lp2 = __ldg(input_logp + ((v * KK + k) << 8) + cat) * LOG2E;
        g_node_q[idx] = (unsigned short)enc1(lp2);
    }
    for (int idx = gtid; idx < LL * NN * CC; idx += NTHREADS) {
        const int l = idx / (NN * CC);
        const int e = __ldg(sum_ch_ids + idx);
        const int2 p = __ldg(prod_ids + (size_t)l * EE + e);
        g_pairs[idx] = make_uint2((unsigned)p.x * ROWB, (unsigned)p.y * ROWB);
    }
    grid_sync();

    // ---------- Phases 1..4: sum layers — cp.async smem pipeline ---------------
    uint2* nqo = reinterpret_cast<uint2*>(g_node_q);
    const char* gbase = reinterpret_cast<const char*>(g_node_q);
    const unsigned c4 = (unsigned)tid;

    unsigned sb[2];
    sb[0] = (unsigned)__cvta_generic_to_shared(&s_buf[0][0]);
    sb[1] = (unsigned)__cvta_generic_to_shared(&s_buf[1][0]);

    const int start = (int)(((long long)blockIdx.x * NN) / GRID_BLOCKS);
    const int end   = (int)(((long long)(blockIdx.x + 1) * NN) / GRID_BLOCKS);
    const int cnt   = end - start;     // 13 or 14

    for (int l = 0; l < LL; l++) {
        const unsigned out_row0 = (unsigned)(NUM_INPUT + l * NN + start);
        const unsigned* gp = reinterpret_cast<const unsigned*>(g_pairs + (size_t)l * NN * CC);
        const float* gw = reinterpret_cast<const float*>(sum_logw + (size_t)l * NN);

        for (int t = tid; t < cnt * 8; t += THREADS)
            s_pairs[t] = gp[start * 8 + t];
        for (int t = tid; t < cnt * 4; t += THREADS)
            reinterpret_cast<float*>(s_w)[t] = gw[start * 4 + t];
        __syncthreads();

        // prologue: two prefetches in flight
        prefetch_node(s_pairs, 0, sb[0], gbase, tid);
        asm volatile("cp.async.commit_group;" ::: "memory");
        prefetch_node(s_pairs, 1, sb[1], gbase, tid);
        asm volatile("cp.async.commit_group;" ::: "memory");

        for (int i = 0; i < cnt; i++) {
            asm volatile("cp.async.wait_group 1;" ::: "memory");
            __syncthreads();                        // buf[i%2] visible to all
            compute_store(sb[i & 1], s_w, i, nqo, out_row0 + i, c4);
            __syncthreads();                        // all done reading buf[i%2]
            if (i + 2 < cnt)
                prefetch_node(s_pairs, i + 2, sb[i & 1], gbase, tid);
            asm volatile("cp.async.commit_group;" ::: "memory");
        }
        asm volatile("cp.async.wait_group 0;" ::: "memory");

        grid_sync();
    }

    // ---------- Phase 5: root partial logsumexp (decode u16, float) -----------
    {
        const unsigned short* last = g_node_q + (size_t)(NUM_INPUT + (LL - 1) * NN) * BB;
        const int idx = gtid;
        if (idx < NCHUNK * BB) {
            const int chunk = idx >> 10;
            const int b = idx & (BB - 1);
            const int n0 = chunk * (NN / NCHUNK);
            float m = -CUDART_INF_F, s = 0.f;
#pragma unroll 4
            for (int i2 = 0; i2 < NN / NCHUNK; i2++) {
                const int n = n0 + i2;
                const float nv = -(float)last[(unsigned)n * BB + b] * INVQ;
                const float x = fmaf(__ldg(root_logw + n), LOG2E, nv);
                const float mn = fmaxf(m, x);
                s = s * ex2(m - mn) + ex2(x - mn);
                m = mn;
            }
            g_partial[chunk * BB + b] = m + lg2(s);
        }
    }
    grid_sync();

    // ---------- Phase 6: final combine (-> natural log) -----------------------
    {
        const int wgid = gtid >> 5;
        const int lane = gtid & 31;
        if (wgid < BB) {
            const int b = wgid;
            const float x0 = g_partial[lane * BB + b];
            const float x1 = g_partial[(lane + 32) * BB + b];
            float m = fmaxf(x0, x1);
#pragma unroll
            for (int o = 16; o > 0; o >>= 1)
                m = fmaxf(m, __shfl_xor_sync(0xFFFFFFFF, m, o));
            float s = ex2(x0 - m) + ex2(x1 - m);
#pragma unroll
            for (int o = 16; o > 0; o >>= 1)
                s += __shfl_xor_sync(0xFFFFFFFF, s, o);
            if (lane == 0) out[b] = (m + lg2(s)) * LN2;
        }
    }
}

// ---------------------------------------------------------------------------
extern "C" void kernel_launch(void* const* d_in, const int* in_sizes, int n_in,
                              void* d_out, int out_size) {
    const int*   inputs     = (const int*)  d_in[0];
    const float* input_logp = (const float*)d_in[1];
    const int*   prod_ids   = (const int*)  d_in[2];  // (L, E, 2)
    const int*   sum_ch_ids = (const int*)  d_in[3];  // (L, N, C)
    const float* sum_logw   = (const float*)d_in[4];  // (L, N, C)
    const float* root_logw  = (const float*)d_in[5];  // (N,)
    float* out = (float*)d_out;

    circuit_kernel<<<GRID_BLOCKS, THREADS>>>(
        inputs, input_logp,
        reinterpret_cast<const int2*>(prod_ids),
        sum_ch_ids,
        reinterpret_cast<const float4*>(sum_logw),
        root_logw, out);
}

// round 13
// speedup vs baseline: 1.0066x; 1.0066x over previous
#include <cuda_runtime.h>
#include <math_constants.h>

// Problem constants
#define NUM_VARS 64
#define KK       32
#define NUM_CATS 256
#define NUM_INPUT (NUM_VARS * KK)   // 2048
#define LL       4
#define EE       16384
#define NN       8192
#define CC       4
#define BB       1024
#define Q4       (BB / 4)           // 256 uint2-groups per row
#define TOTAL_NODES (NUM_INPUT + LL * NN)  // 34816
#define NCHUNK   64
#define MAX_NPB  14                 // max nodes per block per layer

#define GRID_BLOCKS 592             // 4 blocks/SM on 148 SMs — co-resident
#define THREADS     256
#define NTHREADS    (GRID_BLOCKS * THREADS)

#define LOG2E 1.4426950408889634f
#define LN2   0.6931471805599453f
#define QSCALE   128.0f             // u16 = -v_log2 * 128, node clamp 32767
#define INVQ     (1.0f / 128.0f)
// f16x2 magic: (0x6400|d) == 1024+d (f16, exact for d<=1023)
#define H2_MAGIC 0x64006400u
#define H2_A     0xA000A000u        // -1/128 in both halves
#define H2_B     0x48004800u        // +8.0  in both halves
#define DCLAMP   0x03FF03FFu        // d clamp 1023 per halfword
#define OCLAMP   0x7FFF7FFFu        // node-value clamp

// Node pool quantized to u16 (71.3 MB — fully L2-resident)
__device__ unsigned short g_node_q[(size_t)TOTAL_NODES * BB];
__device__ float g_partial[NCHUNK * BB];
__device__ uint2 g_pairs[LL * NN * CC];   // pre-scaled row offsets (row * Q4)
__device__ uint4 g_wq[LL * NN];           // per-child quantized weight, replicated u16x2

// Grid barrier
__device__ unsigned g_bar_count;
__device__ volatile unsigned g_bar_gen;

__device__ __forceinline__ void grid_sync() {
    __syncthreads();
    if (threadIdx.x == 0) {
        __threadfence();
        unsigned gen = g_bar_gen;
        if (atomicAdd(&g_bar_count, 1u) == GRID_BLOCKS - 1u) {
            g_bar_count = 0;
            __threadfence();
            g_bar_gen = gen + 1u;
        } else {
            while (g_bar_gen == gen) { }
        }
    }
    __syncthreads();
    __threadfence();
}

__device__ __forceinline__ float ex2(float x) {
    float r; asm("ex2.approx.ftz.f32 %0, %1;" : "=f"(r) : "f"(x)); return r;
}
__device__ __forceinline__ float lg2(float x) {
    float r; asm("lg2.approx.ftz.f32 %0, %1;" : "=f"(r) : "f"(x)); return r;
}
__device__ __forceinline__ unsigned ex2h2(unsigned h) {
    unsigned r; asm("ex2.approx.f16x2 %0, %1;" : "=r"(r) : "r"(h)); return r;
}
__device__ __forceinline__ unsigned hfma2(unsigned x, unsigned a, unsigned b) {
    unsigned r; asm("fma.rn.f16x2 %0, %1, %2, %3;" : "=r"(r) : "r"(x), "r"(a), "r"(b)); return r;
}
__device__ __forceinline__ unsigned haddh2(unsigned a, unsigned b) {
    unsigned r; asm("add.rn.f16x2 %0, %1, %2;" : "=r"(r) : "r"(a), "r"(b)); return r;
}
__device__ __forceinline__ void unpk(unsigned s, float& lo, float& hi) {
    asm("{\n\t.reg .b16 l, h;\n\tmov.b32 {l, h}, %2;\n\t"
        "cvt.f32.f16 %0, l;\n\tcvt.f32.f16 %1, h;\n\t}"
        : "=f"(lo), "=f"(hi) : "r"(s));
}

// ---- software-pipeline stages ---------------------------------------------
struct Data { uint2 a0, q0, a1, q1, a2, q2, a3, q3; };

__device__ __forceinline__ void gather(Data& d, const unsigned* s_pairs, int i,
                                       const uint2* __restrict__ nq, unsigned c4) {
    const uint4 pa = *reinterpret_cast<const uint4*>(s_pairs + i * 8);
    const uint4 pb = *reinterpret_cast<const uint4*>(s_pairs + i * 8 + 4);
    d.a0 = __ldg(nq + pa.x + c4);
    d.q0 = __ldg(nq + pa.y + c4);
    d.a1 = __ldg(nq + pa.z + c4);
    d.q1 = __ldg(nq + pa.w + c4);
    d.a2 = __ldg(nq + pb.x + c4);
    d.q2 = __ldg(nq + pb.y + c4);
    d.a3 = __ldg(nq + pb.z + c4);
    d.q3 = __ldg(nq + pb.w + c4);
}

// integer LSE over 4 children for one u16x2 word (2 batch columns)
__device__ __forceinline__ unsigned lse_word(unsigned t0, unsigned t1,
                                             unsigned t2, unsigned t3) {
    const unsigned m = __vminu2(__vminu2(t0, t1), __vminu2(t2, t3));
    const unsigned d0 = __vminu2(__vsub2(t0, m), DCLAMP);
    const unsigned d1 = __vminu2(__vsub2(t1, m), DCLAMP);
    const unsigned d2 = __vminu2(__vsub2(t2, m), DCLAMP);
    const unsigned d3 = __vminu2(__vsub2(t3, m), DCLAMP);
    const unsigned e0 = ex2h2(hfma2(d0 | H2_MAGIC, H2_A, H2_B));
    const unsigned e1 = ex2h2(hfma2(d1 | H2_MAGIC, H2_A, H2_B));
    const unsigned e2 = ex2h2(hfma2(d2 | H2_MAGIC, H2_A, H2_B));
    const unsigned e3 = ex2h2(hfma2(d3 | H2_MAGIC, H2_A, H2_B));
    const unsigned s = haddh2(haddh2(e0, e1), haddh2(e2, e3));
    float s0, s1;
    unpk(s, s0, s1);
    const unsigned l0 = __float2uint_rn(lg2(s0) * QSCALE);
    const unsigned l1 = __float2uint_rn(lg2(s1) * QSCALE);
    return __vminu2(__vsubus2(m, l0 | (l1 << 16)), OCLAMP);
}

__device__ __forceinline__ void compute_store(const Data& d, const uint4* s_wq, int i,
                                              uint2* __restrict__ nqo,
                                              unsigned row, unsigned c4) {
    const uint4 w = s_wq[i];   // per-child weight, replicated in both halfwords

    // child totals = pair-sum + weight (saturating u16x2)
    const unsigned t0x = __vaddus2(__vaddus2(d.a0.x, d.q0.x), w.x);
    const unsigned t1x = __vaddus2(__vaddus2(d.a1.x, d.q1.x), w.y);
    const unsigned t2x = __vaddus2(__vaddus2(d.a2.x, d.q2.x), w.z);
    const unsigned t3x = __vaddus2(__vaddus2(d.a3.x, d.q3.x), w.w);
    const unsigned t0y = __vaddus2(__vaddus2(d.a0.y, d.q0.y), w.x);
    const unsigned t1y = __vaddus2(__vaddus2(d.a1.y, d.q1.y), w.y);
    const unsigned t2y = __vaddus2(__vaddus2(d.a2.y, d.q2.y), w.z);
    const unsigned t3y = __vaddus2(__vaddus2(d.a3.y, d.q3.y), w.w);

    uint2 qo;
    qo.x = lse_word(t0x, t1x, t2x, t3x);
    qo.y = lse_word(t0y, t1y, t2y, t3y);
    nqo[row * Q4 + c4] = qo;
}

__global__ void __launch_bounds__(THREADS, 4)
circuit_kernel(const int* __restrict__ inputs,
               const float* __restrict__ input_logp,
               const int2* __restrict__ prod_ids,     // (L, E)
               const int* __restrict__ sum_ch_ids,    // (L, N, C)
               const float4* __restrict__ sum_logw,   // (L, N) as float4
               const float* __restrict__ root_logw,   // (N,)
               float* __restrict__ out) {
    const int gtid = blockIdx.x * THREADS + threadIdx.x;

    __shared__ unsigned s_pairs[MAX_NPB * 8];
    __shared__ uint4    s_wq[MAX_NPB];

    // ---------- Phase 0: input quantize + resolve + weight quantize ------------
    for (int idx = gtid; idx < NUM_INPUT * BB; idx += NTHREADS) {
        const int v = idx >> 15;
        const int k = (idx >> 10) & (KK - 1);
        const int b = idx & (BB - 1);
        const int cat = __ldg(inputs + b * NUM_VARS + v);
        const float lp2 = __ldg(input_logp + ((v * KK + k) << 8) + cat) * LOG2E;
        g_node_q[idx] = (unsigned short)umin(__float2uint_rn(-lp2 * QSCALE), 32767u);
    }
    for (int idx = gtid; idx < LL * NN * CC; idx += NTHREADS) {
        const int l = idx / (NN * CC);
        const int e = __ldg(sum_ch_ids + idx);
        const int2 p = __ldg(prod_ids + (size_t)l * EE + e);
        g_pairs[idx] = make_uint2((unsigned)p.x * Q4, (unsigned)p.y * Q4);
    }
    for (int idx = gtid; idx < LL * NN; idx += NTHREADS) {
        const float4 w = __ldg(sum_logw + idx);
        const unsigned q0 = umin(__float2uint_rn(-w.x * (LOG2E * QSCALE)), 65535u);
        const unsigned q1 = umin(__float2uint_rn(-w.y * (LOG2E * QSCALE)), 65535u);
        const unsigned q2 = umin(__float2uint_rn(-w.z * (LOG2E * QSCALE)), 65535u);
        const unsigned q3 = umin(__float2uint_rn(-w.w * (LOG2E * QSCALE)), 65535u);
        g_wq[idx] = make_uint4(q0 | (q0 << 16), q1 | (q1 << 16),
                               q2 | (q2 << 16), q3 | (q3 << 16));
    }
    grid_sync();

    // ---------- Phases 1..4: sum layers — smem idx + 2-stage pipeline ----------
    const uint2* nq = reinterpret_cast<const uint2*>(g_node_q);
    uint2* nqo = reinterpret_cast<uint2*>(g_node_q);
    const unsigned c4 = threadIdx.x;   // uint2-column 0..255

    const int start = (int)(((long long)blockIdx.x * NN) / GRID_BLOCKS);
    const int end   = (int)(((long long)(blockIdx.x + 1) * NN) / GRID_BLOCKS);
    const int cnt   = end - start;     // 13 or 14

    for (int l = 0; l < LL; l++) {
        const unsigned out_row0 = (unsigned)(NUM_INPUT + l * NN + start);
        const unsigned* gp = reinterpret_cast<const unsigned*>(g_pairs + (size_t)l * NN * CC);
        const unsigned* gwq = reinterpret_cast<const unsigned*>(g_wq + (size_t)l * NN);

        for (int t = threadIdx.x; t < cnt * 8; t += THREADS)
            s_pairs[t] = gp[start * 8 + t];
        for (int t = threadIdx.x; t < cnt * 4; t += THREADS)
            reinterpret_cast<unsigned*>(s_wq)[t] = gwq[start * 4 + t];
        __syncthreads();

        Data dA, dB;
        int i = 0;
        gather(dA, s_pairs, 0, nq, c4);
        while (i + 2 <= cnt) {
            gather(dB, s_pairs, i + 1, nq, c4);
            compute_store(dA, s_wq, i, nqo, out_row0 + i, c4);
            if (i + 2 < cnt)
                gather(dA, s_pairs, i + 2, nq, c4);
            compute_store(dB, s_wq, i + 1, nqo, out_row0 + i + 1, c4);
            i += 2;
        }
        if (i < cnt)
            compute_store(dA, s_wq, i, nqo, out_row0 + i, c4);

        grid_sync();
    }

    // ---------- Phase 5: root partial logsumexp (decode u16, float) -----------
    {
        const unsigned short* last = g_node_q + (size_t)(NUM_INPUT + (LL - 1) * NN) * BB;
        const int idx = gtid;
        if (idx < NCHUNK * BB) {
            const int chunk = idx >> 10;
            const int b = idx & (BB - 1);
            const int n0 = chunk * (NN / NCHUNK);
            float m = -CUDART_INF_F, s = 0.f;
#pragma unroll 4
            for (int i2 = 0; i2 < NN / NCHUNK; i2++) {
                const int n = n0 + i2;
                const float nv = -(float)last[(unsigned)n * BB + b] * INVQ;
                const float x = fmaf(__ldg(root_logw + n), LOG2E, nv);
                const float mn = fmaxf(m, x);
                s = s * ex2(m - mn) + ex2(x - mn);
                m = mn;
            }
            g_partial[chunk * BB + b] = m + lg2(s);
        }
    }
    grid_sync();

    // ---------- Phase 6: final combine (-> natural log) -----------------------
    {
        const int wgid = gtid >> 5;
        const int lane = gtid & 31;
        if (wgid < BB) {
            const int b = wgid;
            const float x0 = g_partial[lane * BB + b];
            const float x1 = g_partial[(lane + 32) * BB + b];
            float m = fmaxf(x0, x1);
#pragma unroll
            for (int o = 16; o > 0; o >>= 1)
                m = fmaxf(m, __shfl_xor_sync(0xFFFFFFFF, m, o));
            float s = ex2(x0 - m) + ex2(x1 - m);
#pragma unroll
            for (int o = 16; o > 0; o >>= 1)
                s += __shfl_xor_sync(0xFFFFFFFF, s, o);
            if (lane == 0) out[b] = (m + lg2(s)) * LN2;
        }
    }
}

// ---------------------------------------------------------------------------
extern "C" void kernel_launch(void* const* d_in, const int* in_sizes, int n_in,
                              void* d_out, int out_size) {
    const int*   inputs     = (const int*)  d_in[0];
    const float* input_logp = (const float*)d_in[1];
    const int*   prod_ids   = (const int*)  d_in[2];  // (L, E, 2)
    const int*   sum_ch_ids = (const int*)  d_in[3];  // (L, N, C)
    const float* sum_logw   = (const float*)d_in[4];  // (L, N, C)
    const float* root_logw  = (const float*)d_in[5];  // (N,)
    float* out = (float*)d_out;

    circuit_kernel<<<GRID_BLOCKS, THREADS>>>(
        inputs, input_logp,
        reinterpret_cast<const int2*>(prod_ids),
        sum_ch_ids,
        reinterpret_cast<const float4*>(sum_logw),
        root_logw, out);
}

// round 14
// speedup vs baseline: 1.1703x; 1.1627x over previous
#include <cuda_runtime.h>
#include <math_constants.h>

// Problem constants
#define NUM_VARS 64
#define KK       32
#define NUM_CATS 256
#define NUM_INPUT (NUM_VARS * KK)   // 2048
#define LL       4
#define EE       16384
#define NN       8192
#define CC       4
#define BB       1024
#define Q16      128                // uint4-groups per row (1024 u16 = 128 x 16B)
#define TOTAL_NODES (NUM_INPUT + LL * NN)  // 34816
#define NCHUNK   64
#define MAX_NPB  14                 // max nodes per block per layer

#define GRID_BLOCKS 592             // 4 blocks/SM on 148 SMs — co-resident
#define THREADS     256
#define NTHREADS    (GRID_BLOCKS * THREADS)

#define LOG2E 1.4426950408889634f
#define LN2   0.6931471805599453f
#define QSCALE   128.0f             // u16 = -v_log2 * 128, clamp 32767
#define INVQ     (1.0f / 128.0f)
#define MAGIC    8388608.0f         // 2^23
#define MAGIC_HI 0x4B000000u

// Node pool quantized to u16 (71.3 MB — fully L2-resident)
__device__ unsigned short g_node_q[(size_t)TOTAL_NODES * BB];
__device__ float g_partial[NCHUNK * BB];
__device__ uint2 g_pairs[LL * NN * CC];   // row offsets pre-scaled by Q16
__device__ float4 g_wqf[LL * NN];         // pre-scaled weights: w*LOG2E + MAGIC*INVQ

// Grid barrier
__device__ unsigned g_bar_count;
__device__ volatile unsigned g_bar_gen;

__device__ __forceinline__ void grid_sync() {
    __syncthreads();
    if (threadIdx.x == 0) {
        __threadfence();                      // release (orders my block's stores)
        unsigned gen = g_bar_gen;
        if (atomicAdd(&g_bar_count, 1u) == GRID_BLOCKS - 1u) {
            g_bar_count = 0;
            __threadfence();
            g_bar_gen = gen + 1u;
        } else {
            while (g_bar_gen == gen) { }
        }
        __threadfence();                      // acquire: SM-wide L1D invalidate
    }
    __syncthreads();
}

__device__ __forceinline__ float ex2(float x) {
    float r; asm("ex2.approx.ftz.f32 %0, %1;" : "=f"(r) : "f"(x)); return r;
}
__device__ __forceinline__ float lg2(float x) {
    float r; asm("lg2.approx.ftz.f32 %0, %1;" : "=f"(r) : "f"(x)); return r;
}
__device__ __forceinline__ float lse4_2(float a, float b, float c, float d) {
    float m = fmaxf(fmaxf(a, b), fmaxf(c, d));
    float s = ex2(a - m) + ex2(b - m) + ex2(c - m) + ex2(d - m);
    return m + lg2(s);
}
__device__ __forceinline__ float dec_lo(unsigned s, float wq) {
    const float f = __uint_as_float(__byte_perm(s, MAGIC_HI, 0x7610));
    return fmaf(f, -INVQ, wq);
}
__device__ __forceinline__ float dec_hi(unsigned s, float wq) {
    const float f = __uint_as_float(__byte_perm(s, MAGIC_HI, 0x7632));
    return fmaf(f, -INVQ, wq);
}
__device__ __forceinline__ unsigned enc1(float v_log2) {
    unsigned q = __float2uint_rn(-v_log2 * QSCALE);
    return umin(q, 32767u);
}

// LSE over 4 children for one u16x2 word (2 batch columns) -> packed u16x2 out
__device__ __forceinline__ unsigned lse_pack(unsigned s0, unsigned s1,
                                             unsigned s2, unsigned s3,
                                             float wq0, float wq1,
                                             float wq2, float wq3) {
    const float x0l = dec_lo(s0, wq0), x0h = dec_hi(s0, wq0);
    const float x1l = dec_lo(s1, wq1), x1h = dec_hi(s1, wq1);
    const float x2l = dec_lo(s2, wq2), x2h = dec_hi(s2, wq2);
    const float x3l = dec_lo(s3, wq3), x3h = dec_hi(s3, wq3);
    const float ol = lse4_2(x0l, x1l, x2l, x3l);
    const float oh = lse4_2(x0h, x1h, x2h, x3h);
    return __byte_perm(enc1(ol), enc1(oh), 0x5410);
}

__global__ void __launch_bounds__(THREADS, 4)
circuit_kernel(const int* __restrict__ inputs,
               const float* __restrict__ input_logp,
               const int2* __restrict__ prod_ids,     // (L, E)
               const int* __restrict__ sum_ch_ids,    // (L, N, C)
               const float4* __restrict__ sum_logw,   // (L, N) as float4
               const float* __restrict__ root_logw,   // (N,)
               float* __restrict__ out) {
    const int gtid = blockIdx.x * THREADS + threadIdx.x;

    __shared__ unsigned s_pairs[MAX_NPB * 8];
    __shared__ float4   s_w[MAX_NPB];

    // ---------- Phase 0: input quantize + resolve + weight prescale ------------
    for (int idx = gtid; idx < NUM_INPUT * BB; idx += NTHREADS) {
        const int v = idx >> 15;
        const int k = (idx >> 10) & (KK - 1);
        const int b = idx & (BB - 1);
        const int cat = __ldg(inputs + b * NUM_VARS + v);
        const float lp2 = __ldg(input_logp + ((v * KK + k) << 8) + cat) * LOG2E;
        g_node_q[idx] = (unsigned short)enc1(lp2);
    }
    for (int idx = gtid; idx < LL * NN * CC; idx += NTHREADS) {
        const int l = idx / (NN * CC);
        const int e = __ldg(sum_ch_ids + idx);
        const int2 p = __ldg(prod_ids + (size_t)l * EE + e);
        g_pairs[idx] = make_uint2((unsigned)p.x * Q16, (unsigned)p.y * Q16);
    }
    for (int idx = gtid; idx < LL * NN; idx += NTHREADS) {
        const float4 w = __ldg(sum_logw + idx);
        float4 wq;
        wq.x = fmaf(w.x, LOG2E, MAGIC * INVQ);
        wq.y = fmaf(w.y, LOG2E, MAGIC * INVQ);
        wq.z = fmaf(w.z, LOG2E, MAGIC * INVQ);
        wq.w = fmaf(w.w, LOG2E, MAGIC * INVQ);
        g_wqf[idx] = wq;
    }
    grid_sync();

    // ---------- Phases 1..4: sum layers — uint4 gathers, half-block per node ---
    const uint4* nq = reinterpret_cast<const uint4*>(g_node_q);
    uint4* nqo = reinterpret_cast<uint4*>(g_node_q);
    const unsigned c16 = threadIdx.x & 127;   // uint4-column 0..127
    const int half = threadIdx.x >> 7;        // 0 or 1: which node of the pair

    const int start = (int)(((long long)blockIdx.x * NN) / GRID_BLOCKS);
    const int end   = (int)(((long long)(blockIdx.x + 1) * NN) / GRID_BLOCKS);
    const int cnt   = end - start;            // 13 or 14
    const int iters = (cnt + 1) >> 1;

    for (int l = 0; l < LL; l++) {
        const int out_base = NUM_INPUT + l * NN;
        const unsigned* gp = reinterpret_cast<const unsigned*>(g_pairs + (size_t)l * NN * CC);
        const float* gw = reinterpret_cast<const float*>(g_wqf + (size_t)l * NN);

        for (int t = threadIdx.x; t < cnt * 8; t += THREADS)
            s_pairs[t] = gp[start * 8 + t];
        for (int t = threadIdx.x; t < cnt * 4; t += THREADS)
            reinterpret_cast<float*>(s_w)[t] = gw[start * 4 + t];
        __syncthreads();

#pragma unroll 2
        for (int i = 0; i < iters; i++) {
            const int local = i * 2 + half;
            const int n = start + local;
            if (n < end) {
                const uint4 pa = *reinterpret_cast<const uint4*>(s_pairs + local * 8);
                const uint4 pb = *reinterpret_cast<const uint4*>(s_pairs + local * 8 + 4);
                const float4 wq = s_w[local];

                const uint4 a0 = __ldg(nq + pa.x + c16);
                const uint4 q0 = __ldg(nq + pa.y + c16);
                const uint4 a1 = __ldg(nq + pa.z + c16);
                const uint4 q1 = __ldg(nq + pa.w + c16);
                const uint4 a2 = __ldg(nq + pb.x + c16);
                const uint4 q2 = __ldg(nq + pb.y + c16);
                const uint4 a3 = __ldg(nq + pb.z + c16);
                const uint4 q3 = __ldg(nq + pb.w + c16);

                uint4 o;
                o.x = lse_pack(__vadd2(a0.x, q0.x), __vadd2(a1.x, q1.x),
                               __vadd2(a2.x, q2.x), __vadd2(a3.x, q3.x),
                               wq.x, wq.y, wq.z, wq.w);
                o.y = lse_pack(__vadd2(a0.y, q0.y), __vadd2(a1.y, q1.y),
                               __vadd2(a2.y, q2.y), __vadd2(a3.y, q3.y),
                               wq.x, wq.y, wq.z, wq.w);
                o.z = lse_pack(__vadd2(a0.z, q0.z), __vadd2(a1.z, q1.z),
                               __vadd2(a2.z, q2.z), __vadd2(a3.z, q3.z),
                               wq.x, wq.y, wq.z, wq.w);
                o.w = lse_pack(__vadd2(a0.w, q0.w), __vadd2(a1.w, q1.w),
                               __vadd2(a2.w, q2.w), __vadd2(a3.w, q3.w),
                               wq.x, wq.y, wq.z, wq.w);

                nqo[(unsigned)(out_base + n) * Q16 + c16] = o;
            }
        }
        grid_sync();
    }

    // ---------- Phase 5: root partial logsumexp (decode u16, float) -----------
    {
        const unsigned short* last = g_node_q + (size_t)(NUM_INPUT + (LL - 1) * NN) * BB;
        const int idx = gtid;
        if (idx < NCHUNK * BB) {
            const int chunk = idx >> 10;
            const int b = idx & (BB - 1);
            const int n0 = chunk * (NN / NCHUNK);
            float m = -CUDART_INF_F, s = 0.f;
#pragma unroll 4
            for (int i2 = 0; i2 < NN / NCHUNK; i2++) {
                const int n = n0 + i2;
                const float nv = -(float)last[(unsigned)n * BB + b] * INVQ;
                const float x = fmaf(__ldg(root_logw + n), LOG2E, nv);
                const float mn = fmaxf(m, x);
                s = s * ex2(m - mn) + ex2(x - mn);
                m = mn;
            }
            g_partial[chunk * BB + b] = m + lg2(s);
        }
    }
    grid_sync();

    // ---------- Phase 6: final combine (-> natural log) -----------------------
    {
        const int wgid = gtid >> 5;
        const int lane = gtid & 31;
        if (wgid < BB) {
            const int b = wgid;
            const float x0 = g_partial[lane * BB + b];
            const float x1 = g_partial[(lane + 32) * BB + b];
            float m = fmaxf(x0, x1);
#pragma unroll
            for (int o = 16; o > 0; o >>= 1)
                m = fmaxf(m, __shfl_xor_sync(0xFFFFFFFF, m, o));
            float s = ex2(x0 - m) + ex2(x1 - m);
#pragma unroll
            for (int o = 16; o > 0; o >>= 1)
                s += __shfl_xor_sync(0xFFFFFFFF, s, o);
            if (lane == 0) out[b] = (m + lg2(s)) * LN2;
        }
    }
}

// ---------------------------------------------------------------------------
extern "C" void kernel_launch(void* const* d_in, const int* in_sizes, int n_in,
                              void* d_out, int out_size) {
    const int*   inputs     = (const int*)  d_in[0];
    const float* input_logp = (const float*)d_in[1];
    const int*   prod_ids   = (const int*)  d_in[2];  // (L, E, 2)
    const int*   sum_ch_ids = (const int*)  d_in[3];  // (L, N, C)
    const float* sum_logw   = (const float*)d_in[4];  // (L, N, C)
    const float* root_logw  = (const float*)d_in[5];  // (N,)
    float* out = (float*)d_out;

    circuit_kernel<<<GRID_BLOCKS, THREADS>>>(
        inputs, input_logp,
        reinterpret_cast<const int2*>(prod_ids),
        sum_ch_ids,
        reinterpret_cast<const float4*>(sum_logw),
        root_logw, out);
}